// round 6
// baseline (speedup 1.0000x reference)
#include <cuda_runtime.h>
#include <cstdint>

#define IN_FEAT   128
#define CODE_DIM  32
#define NUM_CODES 256
#define OUT_FEAT  128

#define TPB 256            // threads per block, 1 row per thread
#define RPB 256            // rows per block

#define TIE_TH 5e-4f       // score-gap threshold for fp64 refinement
#define TIE_CAP (1 << 20)

// Precomputed fused parameters (device globals: no allocation allowed)
__device__ float  g_WcT[IN_FEAT * CODE_DIM];     // [k][j]  (W_pin @ W_down) transposed
__device__ double g_Wc64[IN_FEAT * CODE_DIM];    // fp64 copy for refinement
__device__ float  g_bc [CODE_DIM];               // W_pin @ b_down + b_pin
__device__ double g_bc64[CODE_DIM];
__device__ float  g_cbT[CODE_DIM * NUM_CODES];   // [j][c]  codebook transposed
__device__ float  g_s0 [NUM_CODES];              // cb.bc - 0.5*||cb||^2
__device__ float  g_U  [NUM_CODES * OUT_FEAT];   // cb @ W_pout^T + b_pout
__device__ float  g_T  [NUM_CODES * OUT_FEAT];   // clip(U @ W_up^T + b_up)
__device__ int    g_cnt;                          // near-tie row counter
__device__ int    g_rows[TIE_CAP];                // near-tie row list

// ---- packed f32x2 helpers (sm_103a) ----
using u64 = unsigned long long;
__device__ __forceinline__ u64 pk2(float lo, float hi) {
    u64 r; asm("mov.b64 %0,{%1,%2};" : "=l"(r) : "f"(lo), "f"(hi)); return r;
}
__device__ __forceinline__ void upk2(u64 v, float& lo, float& hi) {
    asm("mov.b64 {%0,%1},%2;" : "=f"(lo), "=f"(hi) : "l"(v));
}
__device__ __forceinline__ u64 ffma2(u64 a, u64 b, u64 c) {
    u64 d; asm("fma.rn.f32x2 %0,%1,%2,%3;" : "=l"(d) : "l"(a), "l"(b), "l"(c)); return d;
}

// =================== precompute kernels (tiny, fp64 accumulation) ===================

__global__ void k_zero() { if (threadIdx.x == 0 && blockIdx.x == 0) g_cnt = 0; }

__global__ void k_pre_wc(const float* __restrict__ Wd, const float* __restrict__ bd,
                         const float* __restrict__ Wp, const float* __restrict__ bp) {
    int t = blockIdx.x * blockDim.x + threadIdx.x;
    if (t < IN_FEAT * CODE_DIM) {
        int m = t >> 5, j = t & 31;
        double s = 0.0;
        for (int k = 0; k < IN_FEAT; k++)
            s += (double)Wp[j * IN_FEAT + k] * (double)Wd[k * IN_FEAT + m];
        g_WcT[m * CODE_DIM + j]  = (float)s;
        g_Wc64[m * CODE_DIM + j] = s;
    }
    if (t < CODE_DIM) {
        double s = (double)bp[t];
        for (int k = 0; k < IN_FEAT; k++)
            s += (double)Wp[t * IN_FEAT + k] * (double)bd[k];
        g_bc[t]   = (float)s;
        g_bc64[t] = s;
    }
}

__global__ void k_pre_cb(const float* __restrict__ cb) {
    int t = blockIdx.x * blockDim.x + threadIdx.x;
    if (t < CODE_DIM * NUM_CODES) {
        int j = t >> 8, c = t & 255;
        g_cbT[j * NUM_CODES + c] = cb[c * CODE_DIM + j];
    }
    if (t < NUM_CODES) {
        double s = 0.0, n2 = 0.0;
        for (int j = 0; j < CODE_DIM; j++) {
            double v = (double)cb[t * CODE_DIM + j];
            s  += v * g_bc64[j];
            n2 += v * v;
        }
        g_s0[t] = (float)(s - 0.5 * n2);
    }
}

__global__ void k_pre_U(const float* __restrict__ cb, const float* __restrict__ Wpo,
                        const float* __restrict__ bpo) {
    int t = blockIdx.x * blockDim.x + threadIdx.x;   // 32768
    int c = t >> 7, o = t & 127;
    float s = bpo[o];
    for (int j = 0; j < CODE_DIM; j++)
        s = fmaf(cb[c * CODE_DIM + j], Wpo[o * CODE_DIM + j], s);
    g_U[c * OUT_FEAT + o] = s;
}

__global__ void k_pre_T(const float* __restrict__ Wu, const float* __restrict__ bu) {
    int t = blockIdx.x * blockDim.x + threadIdx.x;   // 32768
    int c = t >> 7, o = t & 127;
    float s = bu[o];
    for (int i = 0; i < OUT_FEAT; i++)
        s = fmaf(g_U[c * OUT_FEAT + i], Wu[o * OUT_FEAT + i], s);
    g_T[c * OUT_FEAT + o] = fminf(fmaxf(s, -1.0f), 1.0f);
}

// =================== main kernel: 1 row per thread, spill-proof footprint ===================

__global__ __launch_bounds__(TPB, 2)
void k_main(const float* __restrict__ x, float* __restrict__ out,
            int nrows, long long out_size) {
    __shared__ float sWc[IN_FEAT * CODE_DIM];      // 4096 floats [k][j]
    __shared__ float sCb[CODE_DIM * NUM_CODES];    // 8192 floats [j][c]
    __shared__ float sS0[NUM_CODES];               // 256 floats
    __shared__ int   sIdx[RPB];                    // 256 ints

    const int tid  = threadIdx.x;
    const int wid  = tid >> 5;
    const int lane = tid & 31;
    const int rowBase = blockIdx.x * RPB;

    for (int i = tid; i < IN_FEAT * CODE_DIM; i += TPB) sWc[i] = g_WcT[i];
    for (int i = tid; i < CODE_DIM * NUM_CODES; i += TPB) sCb[i] = g_cbT[i];
    if (tid < NUM_CODES) sS0[tid] = g_s0[tid];
    __syncthreads();

    const int gr = rowBase + tid;
    const int grc = (gr < nrows) ? gr : (nrows - 1);   // clamp; result discarded if OOB

    // ---- phase A: z = x_row @ Wc^T  (16 packed f32x2 accumulators over j) ----
    u64 acc[16];
    #pragma unroll
    for (int p = 0; p < 16; p++) acc[p] = 0ull;

    const float4* xr = reinterpret_cast<const float4*>(&x[(size_t)grc * IN_FEAT]);
    #pragma unroll 2
    for (int k4 = 0; k4 < 32; k4++) {
        float4 xv = xr[k4];
        #pragma unroll
        for (int s = 0; s < 4; s++) {
            float xs = (s == 0) ? xv.x : (s == 1) ? xv.y : (s == 2) ? xv.z : xv.w;
            u64 xb = pk2(xs, xs);
            const ulonglong2* wr =
                reinterpret_cast<const ulonglong2*>(&sWc[(k4 * 4 + s) * CODE_DIM]);
            #pragma unroll
            for (int q = 0; q < 8; q++) {
                ulonglong2 w = wr[q];              // broadcast LDS.128
                acc[2 * q]     = ffma2(xb, w.x, acc[2 * q]);
                acc[2 * q + 1] = ffma2(xb, w.y, acc[2 * q + 1]);
            }
        }
    }

    // unpack z to 32 scalars (acc dies here)
    float z[CODE_DIM];
    #pragma unroll
    for (int p = 0; p < 16; p++) upk2(acc[p], z[2 * p], z[2 * p + 1]);

    // ---- phase B: score_c = z . cb_c  (from zero; s0 added at end), argmax + 2nd best ----
    float best = -3.402823466e38f, sec = -3.402823466e38f;
    int bi = 0;

    for (int cc = 0; cc < 8; cc++) {
        u64 sa[16];
        #pragma unroll
        for (int p = 0; p < 16; p++) sa[p] = 0ull;

        #pragma unroll
        for (int j = 0; j < CODE_DIM; j++) {
            u64 zb = pk2(z[j], z[j]);
            const ulonglong2* cw =
                reinterpret_cast<const ulonglong2*>(&sCb[j * NUM_CODES + cc * 32]);
            #pragma unroll
            for (int q = 0; q < 8; q++) {
                ulonglong2 w = cw[q];              // broadcast LDS.128
                sa[2 * q]     = ffma2(zb, w.x, sa[2 * q]);
                sa[2 * q + 1] = ffma2(zb, w.y, sa[2 * q + 1]);
            }
        }
        #pragma unroll
        for (int p = 0; p < 16; p++) {
            int c0 = cc * 32 + 2 * p;
            float a, b;
            upk2(sa[p], a, b);
            a += sS0[c0];
            b += sS0[c0 + 1];
            if (a > best) { sec = best; best = a; bi = c0; }
            else if (a > sec) sec = a;
            if (b > best) { sec = best; best = b; bi = c0 + 1; }
            else if (b > sec) sec = b;
        }
    }

    sIdx[tid] = bi;

    // flag near-tie rows for fp64 refinement
    if (gr < nrows && best - sec < TIE_TH) {
        int p = atomicAdd(&g_cnt, 1);
        if (p < TIE_CAP) g_rows[p] = gr;
    }
    __syncthreads();

    // ---- phase C: outputs (coalesced; table row broadcast from L1/L2) ----
    float* yout = out;
    float* iout = out + (size_t)nrows * OUT_FEAT;
    const bool hasIdx = out_size >= (long long)nrows * (OUT_FEAT + 1);

    const int rb = wid * 32;                 // 8 warps x 32 rows
    #pragma unroll 4
    for (int i = 0; i < 32; i++) {
        int lr = rb + i;
        int g = rowBase + lr;
        if (g < nrows) {
            int idx = sIdx[lr];
            float4 v = *reinterpret_cast<const float4*>(&g_T[idx * OUT_FEAT + lane * 4]);
            *reinterpret_cast<float4*>(&yout[(size_t)g * OUT_FEAT + lane * 4]) = v;
        }
    }
    if (hasIdx && gr < nrows) iout[gr] = (float)sIdx[tid];

    if (blockIdx.x == 0 && tid == 0) {
        long long pos = (long long)nrows * OUT_FEAT + (hasIdx ? nrows : 0);
        for (long long p = pos; p < out_size; p++) out[p] = 0.0f;
    }
}

// =================== fp64 refinement for near-tie rows ===================

__global__ __launch_bounds__(256)
void k_refine(const float* __restrict__ x, const float* __restrict__ cb,
              float* __restrict__ out, int nrows, long long out_size) {
    int nt = g_cnt; if (nt > TIE_CAP) nt = TIE_CAP;
    const bool hasIdx = out_size >= (long long)nrows * (OUT_FEAT + 1);
    float* yout = out;
    float* iout = out + (size_t)nrows * OUT_FEAT;

    for (int i = blockIdx.x * blockDim.x + threadIdx.x; i < nt;
         i += gridDim.x * blockDim.x) {
        int gr = g_rows[i];

        // exact z (fp64 fused)
        double z[CODE_DIM];
        #pragma unroll
        for (int j = 0; j < CODE_DIM; j++) z[j] = g_bc64[j];
        const float* xr = &x[(size_t)gr * IN_FEAT];
        for (int k = 0; k < IN_FEAT; k++) {
            double xv = (double)xr[k];
            const double* wr = &g_Wc64[k * CODE_DIM];
            #pragma unroll
            for (int j = 0; j < CODE_DIM; j++) z[j] += xv * wr[j];
        }

        // exact argmin d2 (== argmax z.c - 0.5||c||^2), first-index tie-break
        double best = -1e300;
        int bi = 0;
        for (int c = 0; c < NUM_CODES; c++) {
            const float* cv = &cb[c * CODE_DIM];
            double s = 0.0, n2 = 0.0;
            #pragma unroll
            for (int j = 0; j < CODE_DIM; j++) {
                double v = (double)cv[j];
                s  += z[j] * v;
                n2 += v * v;
            }
            s -= 0.5 * n2;
            if (s > best) { best = s; bi = c; }
        }

        for (int o = 0; o < OUT_FEAT; o++)
            yout[(size_t)gr * OUT_FEAT + o] = g_T[bi * OUT_FEAT + o];
        if (hasIdx) iout[gr] = (float)bi;
    }
}

// =================== launch ===================

extern "C" void kernel_launch(void* const* d_in, const int* in_sizes, int n_in,
                              void* d_out, int out_size) {
    const float* x   = (const float*)d_in[0];
    const float* Wd  = (const float*)d_in[1];
    const float* bd  = (const float*)d_in[2];
    const float* Wp  = (const float*)d_in[3];
    const float* bp  = (const float*)d_in[4];
    const float* cb  = (const float*)d_in[5];
    const float* Wpo = (const float*)d_in[6];
    const float* bpo = (const float*)d_in[7];
    const float* Wu  = (const float*)d_in[8];
    const float* bu  = (const float*)d_in[9];

    int nrows = in_sizes[0] / IN_FEAT;

    k_zero<<<1, 32>>>();
    k_pre_wc<<<8, 512>>>(Wd, bd, Wp, bp);
    k_pre_cb<<<16, 512>>>(cb);
    k_pre_U<<<64, 512>>>(cb, Wpo, bpo);
    k_pre_T<<<64, 512>>>(Wu, bu);

    int blocks = (nrows + RPB - 1) / RPB;
    if (blocks > 0) {
        k_main<<<blocks, TPB>>>(x, (float*)d_out, nrows, (long long)out_size);
        k_refine<<<128, 256>>>(x, cb, (float*)d_out, nrows, (long long)out_size);
    }
}